// round 6
// baseline (speedup 1.0000x reference)
#include <cuda_runtime.h>
#include <cuda_bf16.h>
#include <math.h>

// Problem constants (fixed instance)
#define BSZ   8
#define NN    2048
#define INC   256
#define HEADS 4
#define OC    128
#define EE    65536
#define MCOLS 136          // 128 (hbar) + 4 (s_src) + 4 (s_dst)
#define ROWS  (BSZ*NN)     // 16384
#define WPR   (NN/32)      // 64 bitset words per dst row
#define BN_EPS 1e-5f

// -------- device scratch (static allocation only; rules forbid cudaMalloc) -----
__device__ unsigned int   g_bits[NN*WPR];          // 512 KB dedupe bitset
__device__ __align__(16) float g_M[INC*MCOLS];     // fused weight matrix
__device__ __align__(16) float g_hbar[ROWS*OC];    // 8 MB head-averaged features
__device__ __align__(16) float g_sS[ROWS*HEADS];
__device__ __align__(16) float g_sD[ROWS*HEADS];
__device__ int            g_cnt[NN];
__device__ int            g_off[NN+1];
__device__ int            g_csr_src[EE];
__device__ float          g_sum[OC], g_sq[OC], g_scale[OC], g_bias[OC];
__device__ int            g_is64;
__device__ unsigned int   g_bn_ticket;

// edge_index may be int64 or int32 depending on JAX x64 config; detected at runtime
__device__ __forceinline__ int edge_at(const void* ei, int idx) {
    if (g_is64) return (int)((const long long*)ei)[idx];
    return ((const int*)ei)[idx];
}

// -------- reset scratch + detect edge dtype (fused; last block does detect) ----
// int64 edge_index (values in [0,2048), non-negative) has all-zero high words.
__global__ void k_reset(const unsigned int* __restrict__ ei32) {
    if (blockIdx.x == gridDim.x - 1) {               // extra block: dtype detect
        __shared__ unsigned int sv;
        if (threadIdx.x == 0) sv = 0u;
        __syncthreads();
        unsigned int v = 0u;
        for (int i = threadIdx.x; i < 8192; i += blockDim.x)
            v |= ei32[2*i + 1];
        atomicOr(&sv, v);
        __syncthreads();
        if (threadIdx.x == 0) { g_is64 = (sv == 0u) ? 1 : 0; g_bn_ticket = 0u; }
        return;
    }
    int i = blockIdx.x * blockDim.x + threadIdx.x;   // covers NN*WPR exactly
    g_bits[i] = 0u;
    if (i < OC) { g_sum[i] = 0.0f; g_sq[i] = 0.0f; }
}

// -------- build fused M = [Wbar | U | V] : [256 x 136] ------------------------
__global__ void k_prep_M(const float* __restrict__ W, const float* __restrict__ a) {
    int k = blockIdx.x;          // 0..255
    int j = threadIdx.x;         // 0..135
    if (j < OC) {
        float s = 0.0f;
        #pragma unroll
        for (int h = 0; h < HEADS; h++) s += W[k*(HEADS*OC) + h*OC + j];
        g_M[k*MCOLS + j] = 0.25f * s;
    } else if (j < MCOLS) {
        int h = (j - OC) & 3;
        const float* av = (j < OC + HEADS) ? a : (a + OC);
        float s = 0.0f;
        #pragma unroll 8
        for (int c = 0; c < OC; c++) s += W[k*(HEADS*OC) + h*OC + c] * av[c];
        g_M[k*MCOLS + j] = s;
    }
}

// -------- GEMM: [16384,256] @ [256,136] -> hbar / s_src / s_dst ---------------
// BM=128, BK=32, 256 threads. Thread (tx=tid&7, ty=tid>>3) owns rows
// {ty, ty+32, ty+64, ty+96} x cols {tx+8j, j<17} => 68 accumulators.
// Per k-step: 4 a-LDS + 17 b-LDS feed 136 FMAs (smem pipe ~= FMA pipe, balanced).
__global__ __launch_bounds__(256) void k_gemm(const float* __restrict__ x) {
    __shared__ __align__(16) float xs[128][33];       // +1 pad: conflict-free
    __shared__ __align__(16) float ms[32*MCOLS];
    const int tid = threadIdx.x;
    const int tx = tid & 7, ty = tid >> 3;            // ty in [0,32)
    const int rowBase = blockIdx.x * 128;

    float acc0[17], acc1[17], acc2[17], acc3[17];
    #pragma unroll
    for (int j = 0; j < 17; j++) { acc0[j]=0.f; acc1[j]=0.f; acc2[j]=0.f; acc3[j]=0.f; }

    for (int kb = 0; kb < INC; kb += 32) {
        // load x tile 128x32 (1024 float4, 4 per thread)
        #pragma unroll
        for (int q = 0; q < 4; q++) {
            int lin = tid + q*256;
            int r = lin >> 3, c4 = (lin & 7) << 2;
            float4 v = *(const float4*)&x[(size_t)(rowBase + r)*INC + kb + c4];
            xs[r][c4+0] = v.x; xs[r][c4+1] = v.y; xs[r][c4+2] = v.z; xs[r][c4+3] = v.w;
        }
        // load M tile 32x136 (1088 float4), contiguous from g_M
        {
            const float4* mp = (const float4*)(g_M + kb*MCOLS);
            float4* sp = (float4*)ms;
            for (int lin = tid; lin < (32*MCOLS)/4; lin += 256) sp[lin] = mp[lin];
        }
        __syncthreads();
        #pragma unroll 4
        for (int kk = 0; kk < 32; kk++) {
            float a0 = xs[ty][kk],    a1 = xs[ty+32][kk];
            float a2 = xs[ty+64][kk], a3 = xs[ty+96][kk];
            float bv[17];
            #pragma unroll
            for (int j = 0; j < 17; j++) bv[j] = ms[kk*MCOLS + tx + 8*j];
            #pragma unroll
            for (int j = 0; j < 17; j++) {
                acc0[j] += a0*bv[j]; acc1[j] += a1*bv[j];
                acc2[j] += a2*bv[j]; acc3[j] += a3*bv[j];
            }
        }
        __syncthreads();
    }
    // epilogue: split columns into hbar / sS / sD
    #pragma unroll
    for (int i = 0; i < 4; i++) {
        int row = rowBase + ty + 32*i;
        float* accp = (i == 0) ? acc0 : (i == 1) ? acc1 : (i == 2) ? acc2 : acc3;
        #pragma unroll
        for (int j = 0; j < 17; j++) {
            int col = tx + 8*j;
            float v = accp[j];
            if (col < OC)              g_hbar[(size_t)row*OC + col] = v;
            else if (col < OC+HEADS)   g_sS[row*HEADS + (col-OC)] = v;
            else                       g_sD[row*HEADS + (col-OC-HEADS)] = v;
        }
    }
}

// -------- mark edges in dedupe bitset (duplicates collapse, as reference .set) -
// Duplicate (src,dst) pairs carry IDENTICAL logits (pair-determined), so the
// edge set == bit set; the CSR built from bits below is fully deterministic.
__global__ void k_mark(const void* ei) {
    int e = blockIdx.x * blockDim.x + threadIdx.x;
    if (e >= EE) return;
    int src = edge_at(ei, e);
    int dst = edge_at(ei, EE + e);
    unsigned int bitpos = (unsigned int)dst * NN + (unsigned int)src;
    atomicOr(&g_bits[bitpos >> 5], 1u << (bitpos & 31));
}

// -------- per-dst degree via popcount (one warp per dst row) ------------------
__global__ void k_count() {
    int warp = (blockIdx.x * blockDim.x + threadIdx.x) >> 5;   // dst
    int lane = threadIdx.x & 31;
    const unsigned int* row = &g_bits[warp * WPR];
    int c = __popc(row[2*lane]) + __popc(row[2*lane + 1]);
    #pragma unroll
    for (int d = 16; d > 0; d >>= 1) c += __shfl_down_sync(0xFFFFFFFFu, c, d);
    if (lane == 0) g_cnt[warp] = c;
}

// -------- exclusive scan over 2048 counts (single block) ----------------------
__global__ void k_scan() {
    __shared__ int bsh[1024];
    int i = threadIdx.x;
    int c0 = g_cnt[2*i], c1 = g_cnt[2*i + 1];
    bsh[i] = c0 + c1;
    __syncthreads();
    for (int d = 1; d < 1024; d <<= 1) {
        int t = (i >= d) ? bsh[i - d] : 0;
        __syncthreads();
        bsh[i] += t;
        __syncthreads();
    }
    int prev = i ? bsh[i-1] : 0;
    g_off[2*i]     = prev;
    g_off[2*i + 1] = prev + c0;
    if (i == 1023) g_off[NN] = bsh[1023];
}

// -------- fill CSR from bitset: sorted by src, deterministic ------------------
// One warp per dst. Lane l owns words 2l, 2l+1 (srcs [64l, 64l+64)); warp
// exclusive scan of per-lane popcounts gives each lane its write base.
__global__ void k_fill() {
    int warp = (blockIdx.x * blockDim.x + threadIdx.x) >> 5;   // dst
    int lane = threadIdx.x & 31;
    const unsigned int* row = &g_bits[warp * WPR];
    unsigned int w0 = row[2*lane], w1 = row[2*lane + 1];
    int c = __popc(w0) + __popc(w1);
    // inclusive warp scan, then convert to exclusive
    int inc = c;
    #pragma unroll
    for (int d = 1; d < 32; d <<= 1) {
        int t = __shfl_up_sync(0xFFFFFFFFu, inc, d);
        if (lane >= d) inc += t;
    }
    int pos = g_off[warp] + (inc - c);
    int base_src = lane * 64;
    while (w0) { int j = __ffs(w0) - 1; w0 &= w0 - 1; g_csr_src[pos++] = base_src + j; }
    base_src += 32;
    while (w1) { int j = __ffs(w1) - 1; w1 &= w1 - 1; g_csr_src[pos++] = base_src + j; }
}

// -------- aggregation with fused softmax weights ------------------------------
// out[b,dst,:] = sum_e (w_e / sum w) * hbar[b,src_e,:]
//   w_e = exp(0.25 * sum_h leaky_relu(sS[b,src,h] + sD[b,dst,h]))
// 4 warps/block; each warp owns one (dst, b) row. Lane l covers channels
// 4l..4l+3 via float4 (32 lanes x 4 = 128 channels). Weights computed at
// staging time (per-lane sS gather + per-row sD broadcast) into shared memory.
__global__ __launch_bounds__(128) void k_aggregate(float* __restrict__ out) {
    __shared__ float sh_w[4][32];
    __shared__ int   sh_src[4][32];
    const int warp = threadIdx.x >> 5;
    const int lane = threadIdx.x & 31;
    const int dst  = blockIdx.x * 4 + warp;
    const int b    = blockIdx.y;
    const int s0 = g_off[dst], s1 = g_off[dst + 1];
    const int bN = b * NN;
    const float4* __restrict__ hb = (const float4*)g_hbar;

    float4 sd = __ldg((const float4*)&g_sD[(size_t)(bN + dst)*HEADS]);

    float4 acc = make_float4(0.f, 0.f, 0.f, 0.f);
    float wsum = 0.f;

    for (int base = s0; base < s1; base += 32) {
        int n = min(32, s1 - base);
        if (lane < n) {
            int src = g_csr_src[base + lane];
            float4 ss = __ldg((const float4*)&g_sS[(size_t)(bN + src)*HEADS]);
            float v0 = ss.x + sd.x, v1 = ss.y + sd.y;
            float v2 = ss.z + sd.z, v3 = ss.w + sd.w;
            float s = ((v0 > 0.f) ? v0 : 0.2f*v0) + ((v1 > 0.f) ? v1 : 0.2f*v1)
                    + ((v2 > 0.f) ? v2 : 0.2f*v2) + ((v3 > 0.f) ? v3 : 0.2f*v3);
            sh_src[warp][lane] = src;
            sh_w[warp][lane]   = expf(0.25f * s);   // mean over 4 heads
        }
        __syncwarp();
        #pragma unroll 4
        for (int i = 0; i < 32; i++) {
            if (i >= n) break;
            int   src = sh_src[warp][i];            // LDS broadcast
            float w   = sh_w[warp][i];
            float4 h = __ldg(&hb[(size_t)(bN + src)*(OC/4) + lane]);
            acc.x += w*h.x; acc.y += w*h.y; acc.z += w*h.z; acc.w += w*h.w;
            wsum += w;
        }
        __syncwarp();
    }
    // Every lane summed the same staged w values => wsum identical across lanes.
    float dinv = (s1 > s0) ? (1.0f / wsum) : 0.0f;
    acc.x *= dinv; acc.y *= dinv; acc.z *= dinv; acc.w *= dinv;
    ((float4*)out)[(size_t)(bN + dst)*(OC/4) + lane] = acc;
}

// -------- batchnorm stats + params (last block computes scale/bias) -----------
__global__ void k_bn_reduce(const float* __restrict__ out,
                            const float* __restrict__ gamma,
                            const float* __restrict__ beta) {
    int c = threadIdx.x;                  // 128
    int r0 = blockIdx.x * 64;
    float s = 0.f, q = 0.f;
    for (int r = 0; r < 64; r++) {
        float v = out[(size_t)(r0 + r)*OC + c];
        s += v; q += v*v;
    }
    atomicAdd(&g_sum[c], s);
    atomicAdd(&g_sq[c],  q);
    __threadfence();
    __shared__ unsigned int amLast;
    __syncthreads();
    if (threadIdx.x == 0)
        amLast = (atomicAdd(&g_bn_ticket, 1u) == gridDim.x - 1) ? 1u : 0u;
    __syncthreads();
    if (amLast) {
        const float inv = 1.0f / (float)ROWS;
        float m   = g_sum[c] * inv;
        float var = g_sq[c] * inv - m*m;
        float sc  = gamma[c] * rsqrtf(var + BN_EPS);
        g_scale[c] = sc;
        g_bias[c]  = beta[c] - m * sc;
    }
}

__global__ void k_elu(float* __restrict__ out) {
    int i = blockIdx.x * blockDim.x + threadIdx.x;   // grid covers 2M exactly
    int c = i & (OC - 1);
    float v = out[i] * g_scale[c] + g_bias[c];
    out[i] = (v > 0.0f) ? v : expm1f(v);             // elu, alpha=1
}

// ------------------------------- launch ---------------------------------------
extern "C" void kernel_launch(void* const* d_in, const int* in_sizes, int n_in,
                              void* d_out, int out_size) {
    const float* x     = (const float*)d_in[0];
    const void*  ei    = d_in[1];                    // int32 or int64, detected
    const float* W     = (const float*)d_in[2];
    const float* a     = (const float*)d_in[3];
    const float* gamma = (const float*)d_in[4];
    const float* beta  = (const float*)d_in[5];
    float* out = (float*)d_out;

    k_reset<<<(NN*WPR)/1024 + 1, 1024>>>((const unsigned int*)ei);
    k_prep_M<<<INC, MCOLS>>>(W, a);
    k_gemm<<<ROWS/128, 256>>>(x);
    k_mark<<<EE/256, 256>>>(ei);
    k_count<<<NN/8, 256>>>();
    k_scan<<<1, 1024>>>();
    k_fill<<<NN/8, 256>>>();
    k_aggregate<<<dim3(NN/4, BSZ), 128>>>(out);
    k_bn_reduce<<<ROWS/64, OC>>>(out, gamma, beta);
    k_elu<<<(ROWS*OC)/256, 256>>>(out);
}